// round 1
// baseline (speedup 1.0000x reference)
#include <cuda_runtime.h>

#define T_LEN   512
#define BATCH   2048
#define HID     64
#define NGATE   256          // 4 * HID
#define NB      16           // batches per block
#define THREADS 128
#define WPAD    66           // padded row stride for w_sh (conflict-free LDS.64)

typedef unsigned long long ull;

__device__ __forceinline__ ull pack2(float x, float y) {
    ull r; asm("mov.b64 %0, {%1, %2};" : "=l"(r) : "f"(x), "f"(y)); return r;
}
__device__ __forceinline__ void unpack2(ull v, float& x, float& y) {
    asm("mov.b64 {%0, %1}, %2;" : "=f"(x), "=f"(y) : "l"(v));
}
// Packed f32x2 FMA (sm_10x FFMA2) — IEEE fp32 per lane, 2x FFMA throughput.
__device__ __forceinline__ ull fma2(ull a, ull b, ull c) {
    ull d; asm("fma.rn.f32x2 %0, %1, %2, %3;" : "=l"(d) : "l"(a), "l"(b), "l"(c));
    return d;
}
__device__ __forceinline__ float sigm(float x) {
    float e = __expf(-x);
    return __fdividef(1.0f, 1.0f + e);
}
__device__ __forceinline__ float tanh_fast(float x) {
    float e = __expf(-2.0f * x);
    return __fdividef(2.0f, 1.0f + e) - 1.0f;
}

__global__ __launch_bounds__(THREADS, 1)
void lstm_kernel(const float* __restrict__ x,
                 const float* __restrict__ w_ih,
                 const float* __restrict__ w_hh,
                 const float* __restrict__ b_ih,
                 const float* __restrict__ b_hh,
                 const float* __restrict__ w_fc,
                 const float* __restrict__ b_fc,
                 float* __restrict__ out)
{
    extern __shared__ float w_sh[];                 // [NGATE][WPAD] = 66 KB
    __shared__ __align__(16) float h_sh[NB][HID];   // 4 KB

    const int tid = threadIdx.x;
    const int tx  = tid & 31;          // lane: hidden units tx and tx+32
    const int ty  = tid >> 5;          // warp: batch group of 4
    const int b0  = blockIdx.x * NB + ty * 4;

    // Stage w_hh [256][64] row-major into padded shared [g][WPAD]
    for (int idx = tid; idx < NGATE * HID; idx += THREADS) {
        int g = idx >> 6, k = idx & 63;
        w_sh[g * WPAD + k] = w_hh[idx];
    }
    // Zero initial hidden state
    for (int idx = tid; idx < NB * HID; idx += THREADS)
        ((float*)h_sh)[idx] = 0.0f;

    // Per-thread weights: gate rows r = tx + 32*m, m=0..7
    // m even -> unit tx, m odd -> unit tx+32; m/2 = gate type (i,f,g,o)
    float wih[8], bias[8];
    #pragma unroll
    for (int m = 0; m < 8; ++m) {
        int r = tx + 32 * m;
        wih[m]  = w_ih[r];             // I == 1
        bias[m] = b_ih[r] + b_hh[r];
    }
    const float wfc0 = w_fc[tx];
    const float wfc1 = w_fc[tx + 32];
    const float bfc  = b_fc[0];

    const float* xp0 = x + (size_t)(b0 + 0) * T_LEN;
    const float* xp1 = x + (size_t)(b0 + 1) * T_LEN;
    const float* xp2 = x + (size_t)(b0 + 2) * T_LEN;
    const float* xp3 = x + (size_t)(b0 + 3) * T_LEN;
    float* op0 = out + (size_t)(b0 + 0) * T_LEN;
    float* op1 = out + (size_t)(b0 + 1) * T_LEN;
    float* op2 = out + (size_t)(b0 + 2) * T_LEN;
    float* op3 = out + (size_t)(b0 + 3) * T_LEN;

    const float* wbase = w_sh + tx * WPAD;
    const float* h0p = h_sh[ty * 4 + 0];
    const float* h1p = h_sh[ty * 4 + 1];
    const float* h2p = h_sh[ty * 4 + 2];
    const float* h3p = h_sh[ty * 4 + 3];

    float c[4][2];
    #pragma unroll
    for (int b = 0; b < 4; ++b) { c[b][0] = 0.0f; c[b][1] = 0.0f; }

    __syncthreads();

    for (int t = 0; t < T_LEN; ++t) {
        const float xv0 = __ldg(xp0 + t);
        const float xv1 = __ldg(xp1 + t);
        const float xv2 = __ldg(xp2 + t);
        const float xv3 = __ldg(xp3 + t);

        // acc halves: .x accumulates even-k products (+ input/bias), .y odd-k
        ull acc[4][8];
        #pragma unroll
        for (int m = 0; m < 8; ++m) {
            acc[0][m] = pack2(fmaf(xv0, wih[m], bias[m]), 0.0f);
            acc[1][m] = pack2(fmaf(xv1, wih[m], bias[m]), 0.0f);
            acc[2][m] = pack2(fmaf(xv2, wih[m], bias[m]), 0.0f);
            acc[3][m] = pack2(fmaf(xv3, wih[m], bias[m]), 0.0f);
        }

        // Recurrent matvec: gates[b][m] += sum_k h[b][k] * w_hh[r][k]
        // k processed in pairs via packed f32x2 FMA.
        #pragma unroll 8
        for (int k = 0; k < HID; k += 2) {
            ull h0v = *(const ull*)(h0p + k);
            ull h1v = *(const ull*)(h1p + k);
            ull h2v = *(const ull*)(h2p + k);
            ull h3v = *(const ull*)(h3p + k);
            #pragma unroll
            for (int m = 0; m < 8; ++m) {
                ull wv = *(const ull*)(wbase + m * (32 * WPAD) + k);
                acc[0][m] = fma2(h0v, wv, acc[0][m]);
                acc[1][m] = fma2(h1v, wv, acc[1][m]);
                acc[2][m] = fma2(h2v, wv, acc[2][m]);
                acc[3][m] = fma2(h3v, wv, acc[3][m]);
            }
        }

        // Gate nonlinearities + state update (PyTorch order i,f,g,o)
        float hnew[4][2];
        #pragma unroll
        for (int b = 0; b < 4; ++b) {
            float gt[8];
            #pragma unroll
            for (int m = 0; m < 8; ++m) {
                float lo, hi;
                unpack2(acc[b][m], lo, hi);
                gt[m] = lo + hi;
            }
            #pragma unroll
            for (int u = 0; u < 2; ++u) {
                float ig = sigm(gt[0 + u]);
                float fg = sigm(gt[2 + u]);
                float gg = tanh_fast(gt[4 + u]);
                float og = sigm(gt[6 + u]);
                float cn = fmaf(fg, c[b][u], ig * gg);
                c[b][u] = cn;
                hnew[b][u] = og * tanh_fast(cn);
            }
        }

        __syncthreads();   // all k-loop reads of old h done before overwrite
        #pragma unroll
        for (int b = 0; b < 4; ++b) {
            h_sh[ty * 4 + b][tx]      = hnew[b][0];
            h_sh[ty * 4 + b][tx + 32] = hnew[b][1];
        }

        // Output head: out[b][t] = h . w_fc + b_fc (warp reduction over units)
        float po[4];
        #pragma unroll
        for (int b = 0; b < 4; ++b)
            po[b] = fmaf(hnew[b][0], wfc0, hnew[b][1] * wfc1);
        #pragma unroll
        for (int off = 16; off > 0; off >>= 1) {
            po[0] += __shfl_xor_sync(0xffffffffu, po[0], off);
            po[1] += __shfl_xor_sync(0xffffffffu, po[1], off);
            po[2] += __shfl_xor_sync(0xffffffffu, po[2], off);
            po[3] += __shfl_xor_sync(0xffffffffu, po[3], off);
        }
        if (tx == 0) {
            op0[t] = po[0] + bfc;
            op1[t] = po[1] + bfc;
            op2[t] = po[2] + bfc;
            op3[t] = po[3] + bfc;
        }
        __syncthreads();   // new h visible before next step's reads
    }
}

extern "C" void kernel_launch(void* const* d_in, const int* in_sizes, int n_in,
                              void* d_out, int out_size)
{
    const float* x    = (const float*)d_in[0];
    const float* w_ih = (const float*)d_in[1];
    const float* w_hh = (const float*)d_in[2];
    const float* b_ih = (const float*)d_in[3];
    const float* b_hh = (const float*)d_in[4];
    const float* w_fc = (const float*)d_in[5];
    const float* b_fc = (const float*)d_in[6];
    float* out = (float*)d_out;

    size_t smem = (size_t)NGATE * WPAD * sizeof(float);  // 67584 B
    cudaFuncSetAttribute(lstm_kernel,
                         cudaFuncAttributeMaxDynamicSharedMemorySize, (int)smem);
    lstm_kernel<<<BATCH / NB, THREADS, smem>>>(x, w_ih, w_hh, b_ih, b_hh,
                                               w_fc, b_fc, out);
}